// round 11
// baseline (speedup 1.0000x reference)
#include <cuda_runtime.h>
#include <cuda_bf16.h>
#include <cuda_fp16.h>
#include <math_constants.h>
#include <cstdint>

// Problem constants
#define B_   4
#define T_   256
#define U_   64
#define DK_  512      // D_ENC == D_DEC
#define F_   1024     // IN_F
#define V_   1024
#define ROWS_ (B_*T_*U_)   // 65536

// Scratch (static __device__ arrays: the sanctioned no-alloc workaround)
__device__ float g_pe[B_*T_*F_];                          // 4 MB
__device__ float g_pd[B_*U_*F_];                          // 1 MB
__device__ __nv_bfloat16 g_A[(size_t)ROWS_ * F_];         // 128 MB  bf16 tanh grid
__device__ __nv_bfloat16 g_WT[(size_t)V_ * F_];           // 2 MB    Wfc^T bf16, K-major
__device__ __half g_logits[(size_t)ROWS_ * V_];           // 128 MB  fp16 logits

__device__ __forceinline__ uint32_t smem_u32(const void* p) {
    uint32_t a;
    asm("{ .reg .u64 t; cvta.to.shared.u64 t, %1; cvt.u32.u64 %0, t; }" : "=r"(a) : "l"(p));
    return a;
}

// ---------------------------------------------------------------------------
// FMA-pipe-only tanh via Lambert continued fraction (MUFU-free).
// ---------------------------------------------------------------------------
__device__ __forceinline__ float ftanh(float x) {
    x = fmaxf(-4.5f, fminf(4.5f, x));
    const float x2 = x * x;
    float n = x2 + 378.0f;
    n = fmaf(n, x2, 17325.0f);
    n = fmaf(n, x2, 135135.0f);
    n = n * x;
    float q = fmaf(x2, 28.0f, 3150.0f);
    q = fmaf(q, x2, 62370.0f);
    q = fmaf(q, x2, 135135.0f);
    float r = __int_as_float(0x7EF311C3 - __float_as_int(q));  // rcp seed
    r = r * fmaf(-q, r, 2.0f);                                 // Newton 1
    r = r * fmaf(-q, r, 2.0f);                                 // Newton 2
    return n * r;
}

__device__ __forceinline__ uint32_t pack_bf16x2(float lo, float hi) {
    uint32_t r;
    asm("cvt.rn.bf16x2.f32 %0, %1, %2;" : "=r"(r) : "f"(hi), "f"(lo));
    return r;
}

// ---------------------------------------------------------------------------
// Merged projection GEMM: blockIdx.y < 16 -> pe (enc @ W_enc), else pd.
// ---------------------------------------------------------------------------
__global__ void __launch_bounds__(256) proj_both(
    const float* __restrict__ enc, const float* __restrict__ W_enc,
    const float* __restrict__ b_enc,
    const float* __restrict__ dec, const float* __restrict__ W_dec,
    const float* __restrict__ b_dec)
{
    __shared__ float Xs[16][64];
    __shared__ float Ws[16][64];

    const int  pe_part = (blockIdx.y < 16);
    const float* X    = pe_part ? enc   : dec;
    const float* W    = pe_part ? W_enc : W_dec;
    const float* bias = pe_part ? b_enc : b_dec;
    float* __restrict__ Y = pe_part ? g_pe : g_pd;
    const int m0 = (pe_part ? blockIdx.y : (blockIdx.y - 16)) * 64;

    const int t  = threadIdx.x;
    const int n0 = blockIdx.x * 64;
    const int tx = t & 15;
    const int ty = t >> 4;
    const int xm = t & 63;
    const int xq = t >> 6;
    const int wk = t >> 4;
    const int wn = (t & 15) * 4;

    float acc[4][4] = {};
    for (int k0 = 0; k0 < DK_; k0 += 16) {
        float4 xv = *(const float4*)&X[(size_t)(m0 + xm) * DK_ + k0 + xq * 4];
        Xs[xq*4+0][xm] = xv.x; Xs[xq*4+1][xm] = xv.y;
        Xs[xq*4+2][xm] = xv.z; Xs[xq*4+3][xm] = xv.w;
        *(float4*)&Ws[wk][wn] = *(const float4*)&W[(size_t)(k0 + wk) * F_ + n0 + wn];
        __syncthreads();
        #pragma unroll
        for (int kk = 0; kk < 16; kk++) {
            float4 av = *(float4*)&Xs[kk][ty*4];
            float4 bv = *(float4*)&Ws[kk][tx*4];
            float a[4] = {av.x, av.y, av.z, av.w};
            float b[4] = {bv.x, bv.y, bv.z, bv.w};
            #pragma unroll
            for (int i = 0; i < 4; i++)
                #pragma unroll
                for (int j = 0; j < 4; j++)
                    acc[i][j] += a[i] * b[j];
        }
        __syncthreads();
    }
    float4 bb = *(const float4*)&bias[n0 + tx*4];
    #pragma unroll
    for (int i = 0; i < 4; i++) {
        float4 o;
        o.x = acc[i][0] + bb.x; o.y = acc[i][1] + bb.y;
        o.z = acc[i][2] + bb.z; o.w = acc[i][3] + bb.w;
        *(float4*)&Y[(size_t)(m0 + ty*4 + i) * F_ + n0 + tx*4] = o;
    }
}

// ---------------------------------------------------------------------------
// Wfc transpose + fp32->bf16: g_WT[v][k] = bf16(W_fc[k][v])
// ---------------------------------------------------------------------------
__global__ void __launch_bounds__(256) transpose_w(const float* __restrict__ W)
{
    __shared__ float tile[32][33];
    const int x0 = blockIdx.x * 32;   // v
    const int y0 = blockIdx.y * 32;   // k
    const int tx = threadIdx.x & 31;
    const int ty = threadIdx.x >> 5;  // 0..7
    #pragma unroll
    for (int i = 0; i < 32; i += 8)
        tile[ty + i][tx] = W[(size_t)(y0 + ty + i) * V_ + x0 + tx];
    __syncthreads();
    #pragma unroll
    for (int i = 0; i < 32; i += 8)
        g_WT[(size_t)(x0 + ty + i) * F_ + y0 + tx] = __float2bfloat16(tile[tx][ty + i]);
}

// ---------------------------------------------------------------------------
// A-build with mask skipping (dead rows never read downstream).
// ---------------------------------------------------------------------------
__global__ void __launch_bounds__(256) build_A(
    const int* __restrict__ enc_lens, const int* __restrict__ dec_lens)
{
    const int bt = blockIdx.x;          // b*T + t
    const int b  = bt >> 8;             // / T_
    const int tt = bt & (T_ - 1);
    if (tt >= enc_lens[b]) return;
    const int ulim = (dec_lens[b] + 1) & ~1;   // round up to 2

    __shared__ float pes[F_];
    const float* per = g_pe + (size_t)bt * F_;
    for (int i = threadIdx.x; i < F_ / 4; i += 256)
        ((float4*)pes)[i] = ((const float4*)per)[i];
    __syncthreads();

    const int k8 = (threadIdx.x & 127) * 8;
    const int uo = threadIdx.x >> 7;    // 0 or 1
    const float* pdb = g_pd + (size_t)(b * U_) * F_;
    __nv_bfloat16* arow = g_A + (size_t)bt * U_ * F_;

    const float4 p0 = *(const float4*)(pes + k8);
    const float4 p1 = *(const float4*)(pes + k8 + 4);

    for (int us = 0; us < ulim; us += 2) {
        const int u = us + uo;
        const float* pdr = pdb + (size_t)u * F_ + k8;
        float4 q0 = *(const float4*)pdr;
        float4 q1 = *(const float4*)(pdr + 4);
        uint4 o;
        o.x = pack_bf16x2(ftanh(p0.x + q0.x), ftanh(p0.y + q0.y));
        o.y = pack_bf16x2(ftanh(p0.z + q0.z), ftanh(p0.w + q0.w));
        o.z = pack_bf16x2(ftanh(p1.x + q1.x), ftanh(p1.y + q1.y));
        o.w = pack_bf16x2(ftanh(p1.z + q1.z), ftanh(p1.w + q1.w));
        *(uint4*)(arow + (size_t)u * F_ + k8) = o;
    }
}

// ---------------------------------------------------------------------------
// Main GEMM via mma.sync (CTA 128x128, warp 64x32, 2 CTA/SM, 3-stage
// cp.async, fp16 epilogue, t-mask CTA skip) + register-level fragment
// pipelining: all 4 A-LDSMs issued as one batch; B fragments double-
// buffered across kk so B(kk+1) loads complete under the 16 MMAs of kk.
// ---------------------------------------------------------------------------
#define KCH    64
#define NSTG   3
#define STG_B  32768          // 16KB A + 16KB B per stage
#define SMEM_GEMM (NSTG * STG_B)   // 96 KB

__global__ void __launch_bounds__(256, 2) joint_gemm_mma(
    const int* __restrict__ enc_lens)
{
    const int row0 = blockIdx.y * 128;
    const int b  = row0 >> 14;
    const int t0 = (row0 >> 6) & (T_ - 1);
    if (t0 >= enc_lens[b]) return;      // whole block dead (uniform branch)

    extern __shared__ char smem[];
    const uint32_t sb = smem_u32(smem);
    const int tid = threadIdx.x;
    const int n0  = blockIdx.x * 128;
    const int w  = tid >> 5, l = tid & 31;
    const int wm = w & 1,  wn = w >> 1;     // 2m x 4n warp grid

    const __nv_bfloat16* Abase = g_A  + (size_t)row0 * F_;
    const __nv_bfloat16* Bbase = g_WT + (size_t)n0   * F_;

    const int lr = tid >> 3;   // 0..31
    const int lu = tid & 7;    // 0..7
    const int lsw = lu ^ (lr & 7);

    auto load_stage = [&](int s, int k0) {
        const uint32_t as_ = sb + (uint32_t)s * STG_B;
        const uint32_t bs_ = as_ + 16384;
        #pragma unroll
        for (int i = 0; i < 4; i++) {
            const int r = lr + i * 32;
            asm volatile("cp.async.cg.shared.global [%0], [%1], 16;"
                :: "r"(as_ + r * 128 + lsw * 16),
                   "l"(Abase + (size_t)r * F_ + k0 + lu * 8));
        }
        #pragma unroll
        for (int i = 0; i < 4; i++) {
            const int r = lr + i * 32;
            asm volatile("cp.async.cg.shared.global [%0], [%1], 16;"
                :: "r"(bs_ + r * 128 + lsw * 16),
                   "l"(Bbase + (size_t)r * F_ + k0 + lu * 8));
        }
        asm volatile("cp.async.commit_group;" ::: "memory");
    };

    const int ar  = l & 15;                      // A: row within m16
    const int akh = l >> 4;                      // A: k-half
    const int br  = (l & 7) + ((l >> 4) << 3);   // B: n within n16
    const int bkh = (l >> 3) & 1;                // B: k-half

    float d[4][4][4] = {};

    load_stage(0, 0);
    load_stage(1, KCH);

    for (int s = 0; s < 16; s++) {
        if (s < 15) asm volatile("cp.async.wait_group 1;" ::: "memory");
        else        asm volatile("cp.async.wait_group 0;" ::: "memory");
        __syncthreads();   // sole barrier; also fences reads of buffer (s-1)%3

        if (s + 2 < 16) load_stage((s + 2) % NSTG, (s + 2) * KCH);

        const uint32_t as_ = sb + (uint32_t)(s % NSTG) * STG_B;
        const uint32_t bs_ = as_ + 16384;

        // B fragment double buffer: bfr[kk&1]
        uint32_t bfr[2][2][4];

        // preload B for kk=0
        #pragma unroll
        for (int j = 0; j < 2; j++) {
            const int n = wn * 32 + j * 16 + br;
            const uint32_t addr = bs_ + n * 128 + (((0 + bkh) ^ (n & 7)) * 16);
            asm volatile("ldmatrix.sync.aligned.m8n8.x4.shared.b16 {%0,%1,%2,%3}, [%4];"
                : "=r"(bfr[0][j][0]), "=r"(bfr[0][j][1]),
                  "=r"(bfr[0][j][2]), "=r"(bfr[0][j][3])
                : "r"(addr));
        }

        #pragma unroll
        for (int kk = 0; kk < 4; kk++) {
            const int cur = kk & 1, nxt = cur ^ 1;

            // Batch-issue all 4 A-LDSMs (latency of 2nd..4th hidden under 1st)
            uint32_t afr[4][4];
            #pragma unroll
            for (int i = 0; i < 4; i++) {
                const int r = wm * 64 + i * 16 + ar;
                const uint32_t addr = as_ + r * 128 + (((kk * 2 + akh) ^ (r & 7)) * 16);
                asm volatile("ldmatrix.sync.aligned.m8n8.x4.shared.b16 {%0,%1,%2,%3}, [%4];"
                    : "=r"(afr[i][0]), "=r"(afr[i][1]), "=r"(afr[i][2]), "=r"(afr[i][3])
                    : "r"(addr));
            }
            // Prefetch B for kk+1 (completes under the 16 MMAs below)
            if (kk < 3) {
                #pragma unroll
                for (int j = 0; j < 2; j++) {
                    const int n = wn * 32 + j * 16 + br;
                    const uint32_t addr = bs_ + n * 128 + ((((kk + 1) * 2 + bkh) ^ (n & 7)) * 16);
                    asm volatile("ldmatrix.sync.aligned.m8n8.x4.shared.b16 {%0,%1,%2,%3}, [%4];"
                        : "=r"(bfr[nxt][j][0]), "=r"(bfr[nxt][j][1]),
                          "=r"(bfr[nxt][j][2]), "=r"(bfr[nxt][j][3])
                        : "r"(addr));
                }
            }
            // 16 MMAs
            #pragma unroll
            for (int i = 0; i < 4; i++) {
                #pragma unroll
                for (int j8 = 0; j8 < 4; j8++) {
                    float* dd = d[i][j8];
                    const uint32_t b0 = bfr[cur][j8 >> 1][(j8 & 1) * 2];
                    const uint32_t b1 = bfr[cur][j8 >> 1][(j8 & 1) * 2 + 1];
                    asm volatile(
                        "mma.sync.aligned.m16n8k16.row.col.f32.bf16.bf16.f32 "
                        "{%0,%1,%2,%3}, {%4,%5,%6,%7}, {%8,%9}, {%0,%1,%2,%3};"
                        : "+f"(dd[0]), "+f"(dd[1]), "+f"(dd[2]), "+f"(dd[3])
                        : "r"(afr[i][0]), "r"(afr[i][1]), "r"(afr[i][2]), "r"(afr[i][3]),
                          "r"(b0), "r"(b1));
                }
            }
        }
    }

    // Epilogue: fp16 logits
    #pragma unroll
    for (int i = 0; i < 4; i++) {
        const int rr = row0 + wm * 64 + i * 16 + (l >> 2);
        #pragma unroll
        for (int j8 = 0; j8 < 4; j8++) {
            const int cc = n0 + wn * 32 + j8 * 8 + 2 * (l & 3);
            *(__half2*)(g_logits + (size_t)rr * V_ + cc) =
                __floats2half2_rn(d[i][j8][0], d[i][j8][1]);
            *(__half2*)(g_logits + (size_t)(rr + 8) * V_ + cc) =
                __floats2half2_rn(d[i][j8][2], d[i][j8][3]);
        }
    }
}

// ---------------------------------------------------------------------------
// Bias + log-softmax + mask, fp16 logits input. One warp per row.
// ---------------------------------------------------------------------------
__global__ void __launch_bounds__(256) softmax_mask_kernel(
    const float* __restrict__ bfc,
    const int* __restrict__ enc_lens, const int* __restrict__ dec_lens,
    float* __restrict__ out)
{
    __shared__ float sbias[V_];
    for (int i = threadIdx.x; i < V_; i += 256) sbias[i] = bfc[i];
    __syncthreads();

    const int warp = threadIdx.x >> 5;
    const int lane = threadIdx.x & 31;
    const int row  = blockIdx.x * 8 + warp;

    const int b  = row >> 14;
    const int tt = (row >> 6) & (T_ - 1);
    const int u  = row & (U_ - 1);

    const uint4*  lrow = (const uint4*)(g_logits + (size_t)row * V_);  // 8 halves each
    float4*       orow = (float4*)(out + (size_t)row * V_);

    const bool ok = (tt < enc_lens[b]) && (u < dec_lens[b]);
    if (!ok) {
        float4 z = make_float4(0.f, 0.f, 0.f, 0.f);
        #pragma unroll
        for (int j = 0; j < 4; j++) {
            const int idx = j * 32 + lane;
            orow[idx*2]   = z;
            orow[idx*2+1] = z;
        }
        return;
    }

    float v[32];
    float mx = -CUDART_INF_F;
    #pragma unroll
    for (int j = 0; j < 4; j++) {
        const int idx = j * 32 + lane;          // covers cols idx*8 .. idx*8+7
        uint4 x = lrow[idx];
        const float4 bb0 = ((const float4*)sbias)[idx*2];
        const float4 bb1 = ((const float4*)sbias)[idx*2+1];
        float2 f0 = __half22float2(*(__half2*)&x.x);
        float2 f1 = __half22float2(*(__half2*)&x.y);
        float2 f2 = __half22float2(*(__half2*)&x.z);
        float2 f3 = __half22float2(*(__half2*)&x.w);
        float* vv = v + j * 8;
        vv[0] = f0.x + bb0.x; vv[1] = f0.y + bb0.y;
        vv[2] = f1.x + bb0.z; vv[3] = f1.y + bb0.w;
        vv[4] = f2.x + bb1.x; vv[5] = f2.y + bb1.y;
        vv[6] = f3.x + bb1.z; vv[7] = f3.y + bb1.w;
        #pragma unroll
        for (int e = 0; e < 8; e++) mx = fmaxf(mx, vv[e]);
    }
    #pragma unroll
    for (int o = 16; o > 0; o >>= 1)
        mx = fmaxf(mx, __shfl_xor_sync(0xFFFFFFFFu, mx, o));

    float s = 0.f;
    #pragma unroll
    for (int i = 0; i < 32; i++) s += __expf(v[i] - mx);
    #pragma unroll
    for (int o = 16; o > 0; o >>= 1)
        s += __shfl_xor_sync(0xFFFFFFFFu, s, o);

    const float lse = mx + logf(s);

    #pragma unroll
    for (int j = 0; j < 4; j++) {
        const int idx = j * 32 + lane;
        const float* vv = v + j * 8;
        orow[idx*2]   = make_float4(vv[0]-lse, vv[1]-lse, vv[2]-lse, vv[3]-lse);
        orow[idx*2+1] = make_float4(vv[4]-lse, vv[5]-lse, vv[6]-lse, vv[7]-lse);
    }
}

// ---------------------------------------------------------------------------
extern "C" void kernel_launch(void* const* d_in, const int* in_sizes, int n_in,
                              void* d_out, int out_size)
{
    const float* enc      = (const float*)d_in[0];
    const float* dec      = (const float*)d_in[1];
    const float* W_enc    = (const float*)d_in[2];
    const float* b_enc    = (const float*)d_in[3];
    const float* W_dec    = (const float*)d_in[4];
    const float* b_dec    = (const float*)d_in[5];
    const float* W_fc     = (const float*)d_in[6];
    const float* b_fc     = (const float*)d_in[7];
    const int*   enc_lens = (const int*)d_in[8];
    const int*   dec_lens = (const int*)d_in[9];
    float* out = (float*)d_out;
    (void)in_sizes; (void)n_in; (void)out_size;

    cudaFuncSetAttribute(joint_gemm_mma,
                         cudaFuncAttributeMaxDynamicSharedMemorySize, SMEM_GEMM);

    // pe = enc @ W_enc + b_enc ; pd = dec @ W_dec + b_dec   (one launch)
    proj_both<<<dim3(F_/64, 20), 256>>>(enc, W_enc, b_enc, dec, W_dec, b_dec);
    // WT = bf16(Wfc^T)
    transpose_w<<<dim3(32, 32), 256>>>(W_fc);
    // A = bf16(tanh(pe (+) pd))  — dead rows skipped
    build_A<<<B_*T_, 256>>>(enc_lens, dec_lens);
    // logits(fp16) = A @ WT^T  — t-masked CTA blocks skipped, frag-pipelined
    joint_gemm_mma<<<dim3(V_/128, ROWS_/128), 256, SMEM_GEMM>>>(enc_lens);
    // out = log_softmax(logits + b_fc) with length masking
    softmax_mask_kernel<<<ROWS_/8, 256>>>(b_fc, enc_lens, dec_lens, out);
}

// round 12
// speedup vs baseline: 1.1675x; 1.1675x over previous
#include <cuda_runtime.h>
#include <cuda_bf16.h>
#include <cuda_fp16.h>
#include <math_constants.h>
#include <cstdint>

// Problem constants
#define B_   4
#define T_   256
#define U_   64
#define DK_  512      // D_ENC == D_DEC
#define F_   1024     // IN_F
#define V_   1024
#define ROWS_ (B_*T_*U_)   // 65536

// Scratch (static __device__ arrays: the sanctioned no-alloc workaround)
__device__ float g_pe[B_*T_*F_];                          // 4 MB
__device__ float g_pd[B_*U_*F_];                          // 1 MB
__device__ __nv_bfloat16 g_A[(size_t)ROWS_ * F_];         // 128 MB  bf16 tanh grid
__device__ __nv_bfloat16 g_WT[(size_t)V_ * F_];           // 2 MB    Wfc^T bf16, K-major
__device__ __half g_logits[(size_t)ROWS_ * V_];           // 128 MB  fp16 logits

__device__ __forceinline__ uint32_t smem_u32(const void* p) {
    uint32_t a;
    asm("{ .reg .u64 t; cvta.to.shared.u64 t, %1; cvt.u32.u64 %0, t; }" : "=r"(a) : "l"(p));
    return a;
}

// ---------------------------------------------------------------------------
// FMA-pipe-only tanh via Lambert continued fraction (MUFU-free).
// ---------------------------------------------------------------------------
__device__ __forceinline__ float ftanh(float x) {
    x = fmaxf(-4.5f, fminf(4.5f, x));
    const float x2 = x * x;
    float n = x2 + 378.0f;
    n = fmaf(n, x2, 17325.0f);
    n = fmaf(n, x2, 135135.0f);
    n = n * x;
    float q = fmaf(x2, 28.0f, 3150.0f);
    q = fmaf(q, x2, 62370.0f);
    q = fmaf(q, x2, 135135.0f);
    float r = __int_as_float(0x7EF311C3 - __float_as_int(q));  // rcp seed
    r = r * fmaf(-q, r, 2.0f);                                 // Newton 1
    r = r * fmaf(-q, r, 2.0f);                                 // Newton 2
    return n * r;
}

__device__ __forceinline__ uint32_t pack_bf16x2(float lo, float hi) {
    uint32_t r;
    asm("cvt.rn.bf16x2.f32 %0, %1, %2;" : "=r"(r) : "f"(hi), "f"(lo));
    return r;
}

// ---------------------------------------------------------------------------
// Merged projection GEMM: blockIdx.y < 16 -> pe (enc @ W_enc), else pd.
// ---------------------------------------------------------------------------
__global__ void __launch_bounds__(256) proj_both(
    const float* __restrict__ enc, const float* __restrict__ W_enc,
    const float* __restrict__ b_enc,
    const float* __restrict__ dec, const float* __restrict__ W_dec,
    const float* __restrict__ b_dec)
{
    __shared__ float Xs[16][64];
    __shared__ float Ws[16][64];

    const int  pe_part = (blockIdx.y < 16);
    const float* X    = pe_part ? enc   : dec;
    const float* W    = pe_part ? W_enc : W_dec;
    const float* bias = pe_part ? b_enc : b_dec;
    float* __restrict__ Y = pe_part ? g_pe : g_pd;
    const int m0 = (pe_part ? blockIdx.y : (blockIdx.y - 16)) * 64;

    const int t  = threadIdx.x;
    const int n0 = blockIdx.x * 64;
    const int tx = t & 15;
    const int ty = t >> 4;
    const int xm = t & 63;
    const int xq = t >> 6;
    const int wk = t >> 4;
    const int wn = (t & 15) * 4;

    float acc[4][4] = {};
    for (int k0 = 0; k0 < DK_; k0 += 16) {
        float4 xv = *(const float4*)&X[(size_t)(m0 + xm) * DK_ + k0 + xq * 4];
        Xs[xq*4+0][xm] = xv.x; Xs[xq*4+1][xm] = xv.y;
        Xs[xq*4+2][xm] = xv.z; Xs[xq*4+3][xm] = xv.w;
        *(float4*)&Ws[wk][wn] = *(const float4*)&W[(size_t)(k0 + wk) * F_ + n0 + wn];
        __syncthreads();
        #pragma unroll
        for (int kk = 0; kk < 16; kk++) {
            float4 av = *(float4*)&Xs[kk][ty*4];
            float4 bv = *(float4*)&Ws[kk][tx*4];
            float a[4] = {av.x, av.y, av.z, av.w};
            float b[4] = {bv.x, bv.y, bv.z, bv.w};
            #pragma unroll
            for (int i = 0; i < 4; i++)
                #pragma unroll
                for (int j = 0; j < 4; j++)
                    acc[i][j] += a[i] * b[j];
        }
        __syncthreads();
    }
    float4 bb = *(const float4*)&bias[n0 + tx*4];
    #pragma unroll
    for (int i = 0; i < 4; i++) {
        float4 o;
        o.x = acc[i][0] + bb.x; o.y = acc[i][1] + bb.y;
        o.z = acc[i][2] + bb.z; o.w = acc[i][3] + bb.w;
        *(float4*)&Y[(size_t)(m0 + ty*4 + i) * F_ + n0 + tx*4] = o;
    }
}

// ---------------------------------------------------------------------------
// Wfc transpose + fp32->bf16: g_WT[v][k] = bf16(W_fc[k][v])
// ---------------------------------------------------------------------------
__global__ void __launch_bounds__(256) transpose_w(const float* __restrict__ W)
{
    __shared__ float tile[32][33];
    const int x0 = blockIdx.x * 32;   // v
    const int y0 = blockIdx.y * 32;   // k
    const int tx = threadIdx.x & 31;
    const int ty = threadIdx.x >> 5;  // 0..7
    #pragma unroll
    for (int i = 0; i < 32; i += 8)
        tile[ty + i][tx] = W[(size_t)(y0 + ty + i) * V_ + x0 + tx];
    __syncthreads();
    #pragma unroll
    for (int i = 0; i < 32; i += 8)
        g_WT[(size_t)(x0 + ty + i) * F_ + y0 + tx] = __float2bfloat16(tile[tx][ty + i]);
}

// ---------------------------------------------------------------------------
// A-build with mask skipping (dead rows never read downstream).
// ---------------------------------------------------------------------------
__global__ void __launch_bounds__(256) build_A(
    const int* __restrict__ enc_lens, const int* __restrict__ dec_lens)
{
    const int bt = blockIdx.x;          // b*T + t
    const int b  = bt >> 8;             // / T_
    const int tt = bt & (T_ - 1);
    if (tt >= enc_lens[b]) return;
    const int ulim = (dec_lens[b] + 1) & ~1;   // round up to 2

    __shared__ float pes[F_];
    const float* per = g_pe + (size_t)bt * F_;
    for (int i = threadIdx.x; i < F_ / 4; i += 256)
        ((float4*)pes)[i] = ((const float4*)per)[i];
    __syncthreads();

    const int k8 = (threadIdx.x & 127) * 8;
    const int uo = threadIdx.x >> 7;    // 0 or 1
    const float* pdb = g_pd + (size_t)(b * U_) * F_;
    __nv_bfloat16* arow = g_A + (size_t)bt * U_ * F_;

    const float4 p0 = *(const float4*)(pes + k8);
    const float4 p1 = *(const float4*)(pes + k8 + 4);

    for (int us = 0; us < ulim; us += 2) {
        const int u = us + uo;
        const float* pdr = pdb + (size_t)u * F_ + k8;
        float4 q0 = *(const float4*)pdr;
        float4 q1 = *(const float4*)(pdr + 4);
        uint4 o;
        o.x = pack_bf16x2(ftanh(p0.x + q0.x), ftanh(p0.y + q0.y));
        o.y = pack_bf16x2(ftanh(p0.z + q0.z), ftanh(p0.w + q0.w));
        o.z = pack_bf16x2(ftanh(p1.x + q1.x), ftanh(p1.y + q1.y));
        o.w = pack_bf16x2(ftanh(p1.z + q1.z), ftanh(p1.w + q1.w));
        *(uint4*)(arow + (size_t)u * F_ + k8) = o;
    }
}

// ---------------------------------------------------------------------------
// Main GEMM via mma.sync with PACKED live rows: both t- and u-masked rows
// are excluded from the M dimension. Each CTA builds a 128-entry row map
// (packed index -> global (b,t,u) row), gathers A rows through per-row
// pointers, and scatters the fp16 epilogue through the map. Live outputs
// are bit-identical to the unpacked GEMM (M rows are independent).
// CTA 128x128, warp 64x32, 2 CTA/SM, 3-stage cp.async, 1 barrier/stage.
// ---------------------------------------------------------------------------
#define KCH    64
#define NSTG   3
#define STG_B  32768          // 16KB A + 16KB B per stage
#define SMEM_GEMM (NSTG * STG_B)   // 96 KB dynamic (+512B static row map)

__global__ void __launch_bounds__(256, 2) joint_gemm_mma(
    const int* __restrict__ enc_lens, const int* __restrict__ dec_lens)
{
    __shared__ int rowmap[128];

    // live-row offsets per b
    int off1, off2, off3, off4;
    {
        const int c0 = enc_lens[0] * dec_lens[0];
        const int c1 = enc_lens[1] * dec_lens[1];
        const int c2 = enc_lens[2] * dec_lens[2];
        const int c3 = enc_lens[3] * dec_lens[3];
        off1 = c0; off2 = off1 + c1; off3 = off2 + c2; off4 = off3 + c3;
    }
    const int row0 = blockIdx.y * 128;
    if (row0 >= off4) return;           // fully past live range

    const int tid = threadIdx.x;

    // Row map: packed index -> global g_A/g_logits row, or -1 if dead.
    if (tid < 128) {
        const int pr = row0 + tid;
        int g = -1;
        if (pr < off4) {
            const int b = (pr >= off1) + (pr >= off2) + (pr >= off3);
            const int base = (b == 0) ? 0 : ((b == 1) ? off1 : ((b == 2) ? off2 : off3));
            const int dl = dec_lens[b];
            const int p = pr - base;
            const int t = p / dl;
            const int u = p - t * dl;
            g = (b << 14) + (t << 6) + u;   // ((b*T + t)*U + u)
        }
        rowmap[tid] = g;
    }
    __syncthreads();

    extern __shared__ char smem[];
    const uint32_t sb = smem_u32(smem);
    const int n0  = blockIdx.x * 128;
    const int w  = tid >> 5, l = tid & 31;
    const int wm = w & 1,  wn = w >> 1;     // 2m x 4n warp grid

    const __nv_bfloat16* Bbase = g_WT + (size_t)n0 * F_;

    const int lr = tid >> 3;   // 0..31
    const int lu = tid & 7;    // 0..7
    const int lsw = lu ^ (lr & 7);

    // Per-row A gather pointers (row 0 fallback for dead rows: valid memory,
    // result rows never written).
    const __nv_bfloat16* aptr[4];
    #pragma unroll
    for (int i = 0; i < 4; i++) {
        int g = rowmap[lr + i * 32];
        if (g < 0) g = 0;
        aptr[i] = g_A + (size_t)g * F_ + lu * 8;
    }

    auto load_stage = [&](int s, int k0) {
        const uint32_t as_ = sb + (uint32_t)s * STG_B;
        const uint32_t bs_ = as_ + 16384;
        #pragma unroll
        for (int i = 0; i < 4; i++) {
            const int r = lr + i * 32;
            asm volatile("cp.async.cg.shared.global [%0], [%1], 16;"
                :: "r"(as_ + r * 128 + lsw * 16), "l"(aptr[i] + k0));
        }
        #pragma unroll
        for (int i = 0; i < 4; i++) {
            const int r = lr + i * 32;
            asm volatile("cp.async.cg.shared.global [%0], [%1], 16;"
                :: "r"(bs_ + r * 128 + lsw * 16),
                   "l"(Bbase + (size_t)r * F_ + k0 + lu * 8));
        }
        asm volatile("cp.async.commit_group;" ::: "memory");
    };

    const int ar  = l & 15;                      // A: row within m16
    const int akh = l >> 4;                      // A: k-half
    const int br  = (l & 7) + ((l >> 4) << 3);   // B: n within n16
    const int bkh = (l >> 3) & 1;                // B: k-half

    float d[4][4][4] = {};

    load_stage(0, 0);
    load_stage(1, KCH);

    for (int s = 0; s < 16; s++) {
        if (s < 15) asm volatile("cp.async.wait_group 1;" ::: "memory");
        else        asm volatile("cp.async.wait_group 0;" ::: "memory");
        __syncthreads();   // sole barrier; also fences reads of buffer (s-1)%3

        if (s + 2 < 16) load_stage((s + 2) % NSTG, (s + 2) * KCH);

        const uint32_t as_ = sb + (uint32_t)(s % NSTG) * STG_B;
        const uint32_t bs_ = as_ + 16384;

        #pragma unroll
        for (int kk = 0; kk < 4; kk++) {
            uint32_t bfr[2][4];
            #pragma unroll
            for (int j = 0; j < 2; j++) {
                const int n = wn * 32 + j * 16 + br;
                const uint32_t addr = bs_ + n * 128 + (((kk * 2 + bkh) ^ (n & 7)) * 16);
                asm volatile("ldmatrix.sync.aligned.m8n8.x4.shared.b16 {%0,%1,%2,%3}, [%4];"
                    : "=r"(bfr[j][0]), "=r"(bfr[j][1]), "=r"(bfr[j][2]), "=r"(bfr[j][3])
                    : "r"(addr));
            }
            #pragma unroll
            for (int i = 0; i < 4; i++) {
                const int r = wm * 64 + i * 16 + ar;
                const uint32_t addr = as_ + r * 128 + (((kk * 2 + akh) ^ (r & 7)) * 16);
                uint32_t a0, a1, a2, a3;
                asm volatile("ldmatrix.sync.aligned.m8n8.x4.shared.b16 {%0,%1,%2,%3}, [%4];"
                    : "=r"(a0), "=r"(a1), "=r"(a2), "=r"(a3) : "r"(addr));
                #pragma unroll
                for (int j8 = 0; j8 < 4; j8++) {
                    float* dd = d[i][j8];
                    const uint32_t b0 = bfr[j8 >> 1][(j8 & 1) * 2];
                    const uint32_t b1 = bfr[j8 >> 1][(j8 & 1) * 2 + 1];
                    asm volatile(
                        "mma.sync.aligned.m16n8k16.row.col.f32.bf16.bf16.f32 "
                        "{%0,%1,%2,%3}, {%4,%5,%6,%7}, {%8,%9}, {%0,%1,%2,%3};"
                        : "+f"(dd[0]), "+f"(dd[1]), "+f"(dd[2]), "+f"(dd[3])
                        : "r"(a0), "r"(a1), "r"(a2), "r"(a3), "r"(b0), "r"(b1));
                }
            }
        }
    }

    // Epilogue: fp16 logits, scattered through the row map.
    #pragma unroll
    for (int i = 0; i < 4; i++) {
        const int lr1 = wm * 64 + i * 16 + (l >> 2);
        const int g1 = rowmap[lr1];
        const int g2 = rowmap[lr1 + 8];
        #pragma unroll
        for (int j8 = 0; j8 < 4; j8++) {
            const int cc = n0 + wn * 32 + j8 * 8 + 2 * (l & 3);
            if (g1 >= 0)
                *(__half2*)(g_logits + (size_t)g1 * V_ + cc) =
                    __floats2half2_rn(d[i][j8][0], d[i][j8][1]);
            if (g2 >= 0)
                *(__half2*)(g_logits + (size_t)g2 * V_ + cc) =
                    __floats2half2_rn(d[i][j8][2], d[i][j8][3]);
        }
    }
}

// ---------------------------------------------------------------------------
// Bias + log-softmax + mask, fp16 logits input. One warp per row.
// ---------------------------------------------------------------------------
__global__ void __launch_bounds__(256) softmax_mask_kernel(
    const float* __restrict__ bfc,
    const int* __restrict__ enc_lens, const int* __restrict__ dec_lens,
    float* __restrict__ out)
{
    __shared__ float sbias[V_];
    for (int i = threadIdx.x; i < V_; i += 256) sbias[i] = bfc[i];
    __syncthreads();

    const int warp = threadIdx.x >> 5;
    const int lane = threadIdx.x & 31;
    const int row  = blockIdx.x * 8 + warp;

    const int b  = row >> 14;
    const int tt = (row >> 6) & (T_ - 1);
    const int u  = row & (U_ - 1);

    const uint4*  lrow = (const uint4*)(g_logits + (size_t)row * V_);  // 8 halves each
    float4*       orow = (float4*)(out + (size_t)row * V_);

    const bool ok = (tt < enc_lens[b]) && (u < dec_lens[b]);
    if (!ok) {
        float4 z = make_float4(0.f, 0.f, 0.f, 0.f);
        #pragma unroll
        for (int j = 0; j < 4; j++) {
            const int idx = j * 32 + lane;
            orow[idx*2]   = z;
            orow[idx*2+1] = z;
        }
        return;
    }

    float v[32];
    float mx = -CUDART_INF_F;
    #pragma unroll
    for (int j = 0; j < 4; j++) {
        const int idx = j * 32 + lane;          // covers cols idx*8 .. idx*8+7
        uint4 x = lrow[idx];
        const float4 bb0 = ((const float4*)sbias)[idx*2];
        const float4 bb1 = ((const float4*)sbias)[idx*2+1];
        float2 f0 = __half22float2(*(__half2*)&x.x);
        float2 f1 = __half22float2(*(__half2*)&x.y);
        float2 f2 = __half22float2(*(__half2*)&x.z);
        float2 f3 = __half22float2(*(__half2*)&x.w);
        float* vv = v + j * 8;
        vv[0] = f0.x + bb0.x; vv[1] = f0.y + bb0.y;
        vv[2] = f1.x + bb0.z; vv[3] = f1.y + bb0.w;
        vv[4] = f2.x + bb1.x; vv[5] = f2.y + bb1.y;
        vv[6] = f3.x + bb1.z; vv[7] = f3.y + bb1.w;
        #pragma unroll
        for (int e = 0; e < 8; e++) mx = fmaxf(mx, vv[e]);
    }
    #pragma unroll
    for (int o = 16; o > 0; o >>= 1)
        mx = fmaxf(mx, __shfl_xor_sync(0xFFFFFFFFu, mx, o));

    float s = 0.f;
    #pragma unroll
    for (int i = 0; i < 32; i++) s += __expf(v[i] - mx);
    #pragma unroll
    for (int o = 16; o > 0; o >>= 1)
        s += __shfl_xor_sync(0xFFFFFFFFu, s, o);

    const float lse = mx + logf(s);

    #pragma unroll
    for (int j = 0; j < 4; j++) {
        const int idx = j * 32 + lane;
        const float* vv = v + j * 8;
        orow[idx*2]   = make_float4(vv[0]-lse, vv[1]-lse, vv[2]-lse, vv[3]-lse);
        orow[idx*2+1] = make_float4(vv[4]-lse, vv[5]-lse, vv[6]-lse, vv[7]-lse);
    }
}

// ---------------------------------------------------------------------------
extern "C" void kernel_launch(void* const* d_in, const int* in_sizes, int n_in,
                              void* d_out, int out_size)
{
    const float* enc      = (const float*)d_in[0];
    const float* dec      = (const float*)d_in[1];
    const float* W_enc    = (const float*)d_in[2];
    const float* b_enc    = (const float*)d_in[3];
    const float* W_dec    = (const float*)d_in[4];
    const float* b_dec    = (const float*)d_in[5];
    const float* W_fc     = (const float*)d_in[6];
    const float* b_fc     = (const float*)d_in[7];
    const int*   enc_lens = (const int*)d_in[8];
    const int*   dec_lens = (const int*)d_in[9];
    float* out = (float*)d_out;
    (void)in_sizes; (void)n_in; (void)out_size;

    cudaFuncSetAttribute(joint_gemm_mma,
                         cudaFuncAttributeMaxDynamicSharedMemorySize, SMEM_GEMM);

    // pe = enc @ W_enc + b_enc ; pd = dec @ W_dec + b_dec   (one launch)
    proj_both<<<dim3(F_/64, 20), 256>>>(enc, W_enc, b_enc, dec, W_dec, b_dec);
    // WT = bf16(Wfc^T)
    transpose_w<<<dim3(32, 32), 256>>>(W_fc);
    // A = bf16(tanh(pe (+) pd))  — dead rows skipped
    build_A<<<B_*T_, 256>>>(enc_lens, dec_lens);
    // logits(fp16) = A @ WT^T  — live rows PACKED in M (t- and u-mask skip)
    joint_gemm_mma<<<dim3(V_/128, ROWS_/128), 256, SMEM_GEMM>>>(enc_lens, dec_lens);
    // out = log_softmax(logits + b_fc) with length masking
    softmax_mask_kernel<<<ROWS_/8, 256>>>(b_fc, enc_lens, dec_lens, out);
}

// round 13
// speedup vs baseline: 1.3493x; 1.1558x over previous
#include <cuda_runtime.h>
#include <cuda_bf16.h>
#include <cuda_fp16.h>
#include <math_constants.h>
#include <cstdint>

// Problem constants
#define B_   4
#define T_   256
#define U_   64
#define DK_  512      // D_ENC == D_DEC
#define F_   1024     // IN_F
#define V_   1024
#define ROWS_ (B_*T_*U_)   // 65536
#define MPROJ 1280         // 1024 pe rows + 256 pd rows

// Scratch (static __device__ arrays: the sanctioned no-alloc workaround)
__device__ float g_proj[(size_t)MPROJ * F_];              // 5 MB  pe rows 0-1023, pd rows 1024-1279
__device__ __nv_bfloat16 g_xbf[(size_t)MPROJ * DK_];      // 1.25 MB  bf16 concat(enc, dec)
__device__ __nv_bfloat16 g_WTe[(size_t)F_ * DK_];         // 1 MB  W_enc^T bf16 [n=1024, k=512]
__device__ __nv_bfloat16 g_WTd[(size_t)F_ * DK_];         // 1 MB  W_dec^T bf16
__device__ __nv_bfloat16 g_A[(size_t)ROWS_ * F_];         // 128 MB  bf16 tanh grid
__device__ __nv_bfloat16 g_WT[(size_t)V_ * F_];           // 2 MB  Wfc^T bf16, K-major
__device__ __half g_logits[(size_t)ROWS_ * V_];           // 128 MB  fp16 logits

__device__ __forceinline__ uint32_t smem_u32(const void* p) {
    uint32_t a;
    asm("{ .reg .u64 t; cvta.to.shared.u64 t, %1; cvt.u32.u64 %0, t; }" : "=r"(a) : "l"(p));
    return a;
}

// ---------------------------------------------------------------------------
// FMA-pipe-only tanh via Lambert continued fraction (MUFU-free).
// ---------------------------------------------------------------------------
__device__ __forceinline__ float ftanh(float x) {
    x = fmaxf(-4.5f, fminf(4.5f, x));
    const float x2 = x * x;
    float n = x2 + 378.0f;
    n = fmaf(n, x2, 17325.0f);
    n = fmaf(n, x2, 135135.0f);
    n = n * x;
    float q = fmaf(x2, 28.0f, 3150.0f);
    q = fmaf(q, x2, 62370.0f);
    q = fmaf(q, x2, 135135.0f);
    float r = __int_as_float(0x7EF311C3 - __float_as_int(q));  // rcp seed
    r = r * fmaf(-q, r, 2.0f);                                 // Newton 1
    r = r * fmaf(-q, r, 2.0f);                                 // Newton 2
    return n * r;
}

__device__ __forceinline__ uint32_t pack_bf16x2(float lo, float hi) {
    uint32_t r;
    asm("cvt.rn.bf16x2.f32 %0, %1, %2;" : "=r"(r) : "f"(hi), "f"(lo));
    return r;
}

// ---------------------------------------------------------------------------
// prep: one launch for all input staging.
//   blocks [0,1024):    W_fc  [1024,1024] -> g_WT  (32x32 tiles)
//   blocks [1024,1536): W_enc [512,1024]  -> g_WTe (32x32 tiles, 16 k-tiles)
//   blocks [1536,2048): W_dec [512,1024]  -> g_WTd
//   blocks [2048,2368): linear fp32->bf16 convert of concat(enc,dec) -> g_xbf
// ---------------------------------------------------------------------------
__global__ void __launch_bounds__(256) prep(
    const float* __restrict__ W_fc, const float* __restrict__ W_enc,
    const float* __restrict__ W_dec, const float* __restrict__ enc,
    const float* __restrict__ dec)
{
    const int bid = blockIdx.x;
    if (bid < 2048) {
        __shared__ float tile[32][33];
        const float* W;  __nv_bfloat16* D;  int bx, by, kdim;
        if (bid < 1024) { W = W_fc;  D = g_WT;  bx = bid & 31;          by = bid >> 5;          kdim = F_;  }
        else if (bid < 1536) { W = W_enc; D = g_WTe; bx = (bid-1024) & 31; by = (bid-1024) >> 5; kdim = DK_; }
        else { W = W_dec; D = g_WTd; bx = (bid-1536) & 31; by = (bid-1536) >> 5; kdim = DK_; }
        const int x0 = bx * 32;   // n (output-row dim)
        const int y0 = by * 32;   // k
        const int tx = threadIdx.x & 31;
        const int ty = threadIdx.x >> 5;  // 0..7
        #pragma unroll
        for (int i = 0; i < 32; i += 8)
            tile[ty + i][tx] = W[(size_t)(y0 + ty + i) * F_ + x0 + tx];
        __syncthreads();
        #pragma unroll
        for (int i = 0; i < 32; i += 8)
            D[(size_t)(x0 + ty + i) * kdim + y0 + tx] = __float2bfloat16(tile[tx][ty + i]);
    } else {
        // convert: 655360 elems, 320 blocks x 2048 elems; enc = first 524288
        const int cid = bid - 2048;
        const size_t base = (size_t)cid * 2048 + threadIdx.x * 8;
        const float* src = (base < (size_t)1024 * DK_) ? (enc + base)
                                                       : (dec + (base - (size_t)1024 * DK_));
        float4 a = *(const float4*)src;
        float4 b = *(const float4*)(src + 4);
        uint4 o;
        o.x = pack_bf16x2(a.x, a.y);  o.y = pack_bf16x2(a.z, a.w);
        o.z = pack_bf16x2(b.x, b.y);  o.w = pack_bf16x2(b.z, b.w);
        *(uint4*)(g_xbf + base) = o;
    }
}

// ---------------------------------------------------------------------------
// proj_mma: g_proj[0:1280, 0:1024] = concat(enc,dec)_bf16 @ {W_enc,W_dec}^T + bias
// Same machinery as joint GEMM: CTA 128x128, warp 64x32, 3-stage cp.async,
// K=512 (8 stages). blockIdx.y<8 -> pe part (g_WTe, b_enc), else pd part.
// ---------------------------------------------------------------------------
#define KCH    64
#define NSTG   3
#define STG_B  32768          // 16KB A + 16KB B per stage
#define SMEM_GEMM (NSTG * STG_B)   // 96 KB

__global__ void __launch_bounds__(256, 2) proj_mma(
    const float* __restrict__ b_enc, const float* __restrict__ b_dec)
{
    extern __shared__ char smem[];
    const uint32_t sb = smem_u32(smem);
    const int tid = threadIdx.x;
    const int n0   = blockIdx.x * 128;
    const int row0 = blockIdx.y * 128;
    const bool pe_part = (blockIdx.y < 8);
    const int w  = tid >> 5, l = tid & 31;
    const int wm = w & 1,  wn = w >> 1;

    const __nv_bfloat16* Abase = g_xbf + (size_t)row0 * DK_;
    const __nv_bfloat16* Bbase = (pe_part ? g_WTe : g_WTd) + (size_t)n0 * DK_;
    const float* bias = pe_part ? b_enc : b_dec;

    const int lr = tid >> 3;
    const int lu = tid & 7;
    const int lsw = lu ^ (lr & 7);

    auto load_stage = [&](int s, int k0) {
        const uint32_t as_ = sb + (uint32_t)s * STG_B;
        const uint32_t bs_ = as_ + 16384;
        #pragma unroll
        for (int i = 0; i < 4; i++) {
            const int r = lr + i * 32;
            asm volatile("cp.async.cg.shared.global [%0], [%1], 16;"
                :: "r"(as_ + r * 128 + lsw * 16),
                   "l"(Abase + (size_t)r * DK_ + k0 + lu * 8));
        }
        #pragma unroll
        for (int i = 0; i < 4; i++) {
            const int r = lr + i * 32;
            asm volatile("cp.async.cg.shared.global [%0], [%1], 16;"
                :: "r"(bs_ + r * 128 + lsw * 16),
                   "l"(Bbase + (size_t)r * DK_ + k0 + lu * 8));
        }
        asm volatile("cp.async.commit_group;" ::: "memory");
    };

    const int ar  = l & 15;
    const int akh = l >> 4;
    const int br  = (l & 7) + ((l >> 4) << 3);
    const int bkh = (l >> 3) & 1;

    float d[4][4][4] = {};

    load_stage(0, 0);
    load_stage(1, KCH);

    #define NS_PROJ 8
    for (int s = 0; s < NS_PROJ; s++) {
        if (s < NS_PROJ - 1) asm volatile("cp.async.wait_group 1;" ::: "memory");
        else                 asm volatile("cp.async.wait_group 0;" ::: "memory");
        __syncthreads();

        if (s + 2 < NS_PROJ) load_stage((s + 2) % NSTG, (s + 2) * KCH);

        const uint32_t as_ = sb + (uint32_t)(s % NSTG) * STG_B;
        const uint32_t bs_ = as_ + 16384;

        #pragma unroll
        for (int kk = 0; kk < 4; kk++) {
            uint32_t bfr[2][4];
            #pragma unroll
            for (int j = 0; j < 2; j++) {
                const int n = wn * 32 + j * 16 + br;
                const uint32_t addr = bs_ + n * 128 + (((kk * 2 + bkh) ^ (n & 7)) * 16);
                asm volatile("ldmatrix.sync.aligned.m8n8.x4.shared.b16 {%0,%1,%2,%3}, [%4];"
                    : "=r"(bfr[j][0]), "=r"(bfr[j][1]), "=r"(bfr[j][2]), "=r"(bfr[j][3])
                    : "r"(addr));
            }
            #pragma unroll
            for (int i = 0; i < 4; i++) {
                const int r = wm * 64 + i * 16 + ar;
                const uint32_t addr = as_ + r * 128 + (((kk * 2 + akh) ^ (r & 7)) * 16);
                uint32_t a0, a1, a2, a3;
                asm volatile("ldmatrix.sync.aligned.m8n8.x4.shared.b16 {%0,%1,%2,%3}, [%4];"
                    : "=r"(a0), "=r"(a1), "=r"(a2), "=r"(a3) : "r"(addr));
                #pragma unroll
                for (int j8 = 0; j8 < 4; j8++) {
                    float* dd = d[i][j8];
                    const uint32_t b0 = bfr[j8 >> 1][(j8 & 1) * 2];
                    const uint32_t b1 = bfr[j8 >> 1][(j8 & 1) * 2 + 1];
                    asm volatile(
                        "mma.sync.aligned.m16n8k16.row.col.f32.bf16.bf16.f32 "
                        "{%0,%1,%2,%3}, {%4,%5,%6,%7}, {%8,%9}, {%0,%1,%2,%3};"
                        : "+f"(dd[0]), "+f"(dd[1]), "+f"(dd[2]), "+f"(dd[3])
                        : "r"(a0), "r"(a1), "r"(a2), "r"(a3), "r"(b0), "r"(b1));
                }
            }
        }
    }

    // Epilogue: fp32 + bias
    #pragma unroll
    for (int i = 0; i < 4; i++) {
        const int rr = row0 + wm * 64 + i * 16 + (l >> 2);
        #pragma unroll
        for (int j8 = 0; j8 < 4; j8++) {
            const int cc = n0 + wn * 32 + j8 * 8 + 2 * (l & 3);
            const float bx = bias[cc], by = bias[cc + 1];
            *(float2*)(g_proj + (size_t)rr * F_ + cc) =
                make_float2(d[i][j8][0] + bx, d[i][j8][1] + by);
            *(float2*)(g_proj + (size_t)(rr + 8) * F_ + cc) =
                make_float2(d[i][j8][2] + bx, d[i][j8][3] + by);
        }
    }
}

// ---------------------------------------------------------------------------
// A-build with mask skipping (dead rows never read downstream).
// pe = g_proj[bt], pd = g_proj[1024 + b*U + u].
// ---------------------------------------------------------------------------
__global__ void __launch_bounds__(256) build_A(
    const int* __restrict__ enc_lens, const int* __restrict__ dec_lens)
{
    const int bt = blockIdx.x;          // b*T + t
    const int b  = bt >> 8;             // / T_
    const int tt = bt & (T_ - 1);
    if (tt >= enc_lens[b]) return;
    const int ulim = (dec_lens[b] + 1) & ~1;   // round up to 2

    __shared__ float pes[F_];
    const float* per = g_proj + (size_t)bt * F_;
    for (int i = threadIdx.x; i < F_ / 4; i += 256)
        ((float4*)pes)[i] = ((const float4*)per)[i];
    __syncthreads();

    const int k8 = (threadIdx.x & 127) * 8;
    const int uo = threadIdx.x >> 7;    // 0 or 1
    const float* pdb = g_proj + (size_t)(1024 + b * U_) * F_;
    __nv_bfloat16* arow = g_A + (size_t)bt * U_ * F_;

    const float4 p0 = *(const float4*)(pes + k8);
    const float4 p1 = *(const float4*)(pes + k8 + 4);

    for (int us = 0; us < ulim; us += 2) {
        const int u = us + uo;
        const float* pdr = pdb + (size_t)u * F_ + k8;
        float4 q0 = *(const float4*)pdr;
        float4 q1 = *(const float4*)(pdr + 4);
        uint4 o;
        o.x = pack_bf16x2(ftanh(p0.x + q0.x), ftanh(p0.y + q0.y));
        o.y = pack_bf16x2(ftanh(p0.z + q0.z), ftanh(p0.w + q0.w));
        o.z = pack_bf16x2(ftanh(p1.x + q1.x), ftanh(p1.y + q1.y));
        o.w = pack_bf16x2(ftanh(p1.z + q1.z), ftanh(p1.w + q1.w));
        *(uint4*)(arow + (size_t)u * F_ + k8) = o;
    }
}

// ---------------------------------------------------------------------------
// Main GEMM via mma.sync with PACKED live rows (R11, unchanged — 224us,
// tensor 67%): CTA 128x128, warp 64x32, 2 CTA/SM, 3-stage cp.async,
// row map gathers A and scatters fp16 logits.
// ---------------------------------------------------------------------------
__global__ void __launch_bounds__(256, 2) joint_gemm_mma(
    const int* __restrict__ enc_lens, const int* __restrict__ dec_lens)
{
    __shared__ int rowmap[128];

    int off1, off2, off3, off4;
    {
        const int c0 = enc_lens[0] * dec_lens[0];
        const int c1 = enc_lens[1] * dec_lens[1];
        const int c2 = enc_lens[2] * dec_lens[2];
        const int c3 = enc_lens[3] * dec_lens[3];
        off1 = c0; off2 = off1 + c1; off3 = off2 + c2; off4 = off3 + c3;
    }
    const int row0 = blockIdx.y * 128;
    if (row0 >= off4) return;

    const int tid = threadIdx.x;

    if (tid < 128) {
        const int pr = row0 + tid;
        int g = -1;
        if (pr < off4) {
            const int b = (pr >= off1) + (pr >= off2) + (pr >= off3);
            const int base = (b == 0) ? 0 : ((b == 1) ? off1 : ((b == 2) ? off2 : off3));
            const int dl = dec_lens[b];
            const int p = pr - base;
            const int t = p / dl;
            const int u = p - t * dl;
            g = (b << 14) + (t << 6) + u;
        }
        rowmap[tid] = g;
    }
    __syncthreads();

    extern __shared__ char smem[];
    const uint32_t sb = smem_u32(smem);
    const int n0  = blockIdx.x * 128;
    const int w  = tid >> 5, l = tid & 31;
    const int wm = w & 1,  wn = w >> 1;

    const __nv_bfloat16* Bbase = g_WT + (size_t)n0 * F_;

    const int lr = tid >> 3;
    const int lu = tid & 7;
    const int lsw = lu ^ (lr & 7);

    const __nv_bfloat16* aptr[4];
    #pragma unroll
    for (int i = 0; i < 4; i++) {
        int g = rowmap[lr + i * 32];
        if (g < 0) g = 0;
        aptr[i] = g_A + (size_t)g * F_ + lu * 8;
    }

    auto load_stage = [&](int s, int k0) {
        const uint32_t as_ = sb + (uint32_t)s * STG_B;
        const uint32_t bs_ = as_ + 16384;
        #pragma unroll
        for (int i = 0; i < 4; i++) {
            const int r = lr + i * 32;
            asm volatile("cp.async.cg.shared.global [%0], [%1], 16;"
                :: "r"(as_ + r * 128 + lsw * 16), "l"(aptr[i] + k0));
        }
        #pragma unroll
        for (int i = 0; i < 4; i++) {
            const int r = lr + i * 32;
            asm volatile("cp.async.cg.shared.global [%0], [%1], 16;"
                :: "r"(bs_ + r * 128 + lsw * 16),
                   "l"(Bbase + (size_t)r * F_ + k0 + lu * 8));
        }
        asm volatile("cp.async.commit_group;" ::: "memory");
    };

    const int ar  = l & 15;
    const int akh = l >> 4;
    const int br  = (l & 7) + ((l >> 4) << 3);
    const int bkh = (l >> 3) & 1;

    float d[4][4][4] = {};

    load_stage(0, 0);
    load_stage(1, KCH);

    for (int s = 0; s < 16; s++) {
        if (s < 15) asm volatile("cp.async.wait_group 1;" ::: "memory");
        else        asm volatile("cp.async.wait_group 0;" ::: "memory");
        __syncthreads();

        if (s + 2 < 16) load_stage((s + 2) % NSTG, (s + 2) * KCH);

        const uint32_t as_ = sb + (uint32_t)(s % NSTG) * STG_B;
        const uint32_t bs_ = as_ + 16384;

        #pragma unroll
        for (int kk = 0; kk < 4; kk++) {
            uint32_t bfr[2][4];
            #pragma unroll
            for (int j = 0; j < 2; j++) {
                const int n = wn * 32 + j * 16 + br;
                const uint32_t addr = bs_ + n * 128 + (((kk * 2 + bkh) ^ (n & 7)) * 16);
                asm volatile("ldmatrix.sync.aligned.m8n8.x4.shared.b16 {%0,%1,%2,%3}, [%4];"
                    : "=r"(bfr[j][0]), "=r"(bfr[j][1]), "=r"(bfr[j][2]), "=r"(bfr[j][3])
                    : "r"(addr));
            }
            #pragma unroll
            for (int i = 0; i < 4; i++) {
                const int r = wm * 64 + i * 16 + ar;
                const uint32_t addr = as_ + r * 128 + (((kk * 2 + akh) ^ (r & 7)) * 16);
                uint32_t a0, a1, a2, a3;
                asm volatile("ldmatrix.sync.aligned.m8n8.x4.shared.b16 {%0,%1,%2,%3}, [%4];"
                    : "=r"(a0), "=r"(a1), "=r"(a2), "=r"(a3) : "r"(addr));
                #pragma unroll
                for (int j8 = 0; j8 < 4; j8++) {
                    float* dd = d[i][j8];
                    const uint32_t b0 = bfr[j8 >> 1][(j8 & 1) * 2];
                    const uint32_t b1 = bfr[j8 >> 1][(j8 & 1) * 2 + 1];
                    asm volatile(
                        "mma.sync.aligned.m16n8k16.row.col.f32.bf16.bf16.f32 "
                        "{%0,%1,%2,%3}, {%4,%5,%6,%7}, {%8,%9}, {%0,%1,%2,%3};"
                        : "+f"(dd[0]), "+f"(dd[1]), "+f"(dd[2]), "+f"(dd[3])
                        : "r"(a0), "r"(a1), "r"(a2), "r"(a3), "r"(b0), "r"(b1));
                }
            }
        }
    }

    #pragma unroll
    for (int i = 0; i < 4; i++) {
        const int lr1 = wm * 64 + i * 16 + (l >> 2);
        const int g1 = rowmap[lr1];
        const int g2 = rowmap[lr1 + 8];
        #pragma unroll
        for (int j8 = 0; j8 < 4; j8++) {
            const int cc = n0 + wn * 32 + j8 * 8 + 2 * (l & 3);
            if (g1 >= 0)
                *(__half2*)(g_logits + (size_t)g1 * V_ + cc) =
                    __floats2half2_rn(d[i][j8][0], d[i][j8][1]);
            if (g2 >= 0)
                *(__half2*)(g_logits + (size_t)g2 * V_ + cc) =
                    __floats2half2_rn(d[i][j8][2], d[i][j8][3]);
        }
    }
}

// ---------------------------------------------------------------------------
// Bias + log-softmax + mask, fp16 logits input. One warp per row.
// ---------------------------------------------------------------------------
__global__ void __launch_bounds__(256) softmax_mask_kernel(
    const float* __restrict__ bfc,
    const int* __restrict__ enc_lens, const int* __restrict__ dec_lens,
    float* __restrict__ out)
{
    __shared__ float sbias[V_];
    for (int i = threadIdx.x; i < V_; i += 256) sbias[i] = bfc[i];
    __syncthreads();

    const int warp = threadIdx.x >> 5;
    const int lane = threadIdx.x & 31;
    const int row  = blockIdx.x * 8 + warp;

    const int b  = row >> 14;
    const int tt = (row >> 6) & (T_ - 1);
    const int u  = row & (U_ - 1);

    const uint4*  lrow = (const uint4*)(g_logits + (size_t)row * V_);
    float4*       orow = (float4*)(out + (size_t)row * V_);

    const bool ok = (tt < enc_lens[b]) && (u < dec_lens[b]);
    if (!ok) {
        float4 z = make_float4(0.f, 0.f, 0.f, 0.f);
        #pragma unroll
        for (int j = 0; j < 4; j++) {
            const int idx = j * 32 + lane;
            orow[idx*2]   = z;
            orow[idx*2+1] = z;
        }
        return;
    }

    float v[32];
    float mx = -CUDART_INF_F;
    #pragma unroll
    for (int j = 0; j < 4; j++) {
        const int idx = j * 32 + lane;
        uint4 x = lrow[idx];
        const float4 bb0 = ((const float4*)sbias)[idx*2];
        const float4 bb1 = ((const float4*)sbias)[idx*2+1];
        float2 f0 = __half22float2(*(__half2*)&x.x);
        float2 f1 = __half22float2(*(__half2*)&x.y);
        float2 f2 = __half22float2(*(__half2*)&x.z);
        float2 f3 = __half22float2(*(__half2*)&x.w);
        float* vv = v + j * 8;
        vv[0] = f0.x + bb0.x; vv[1] = f0.y + bb0.y;
        vv[2] = f1.x + bb0.z; vv[3] = f1.y + bb0.w;
        vv[4] = f2.x + bb1.x; vv[5] = f2.y + bb1.y;
        vv[6] = f3.x + bb1.z; vv[7] = f3.y + bb1.w;
        #pragma unroll
        for (int e = 0; e < 8; e++) mx = fmaxf(mx, vv[e]);
    }
    #pragma unroll
    for (int o = 16; o > 0; o >>= 1)
        mx = fmaxf(mx, __shfl_xor_sync(0xFFFFFFFFu, mx, o));

    float s = 0.f;
    #pragma unroll
    for (int i = 0; i < 32; i++) s += __expf(v[i] - mx);
    #pragma unroll
    for (int o = 16; o > 0; o >>= 1)
        s += __shfl_xor_sync(0xFFFFFFFFu, s, o);

    const float lse = mx + logf(s);

    #pragma unroll
    for (int j = 0; j < 4; j++) {
        const int idx = j * 32 + lane;
        const float* vv = v + j * 8;
        orow[idx*2]   = make_float4(vv[0]-lse, vv[1]-lse, vv[2]-lse, vv[3]-lse);
        orow[idx*2+1] = make_float4(vv[4]-lse, vv[5]-lse, vv[6]-lse, vv[7]-lse);
    }
}

// ---------------------------------------------------------------------------
extern "C" void kernel_launch(void* const* d_in, const int* in_sizes, int n_in,
                              void* d_out, int out_size)
{
    const float* enc      = (const float*)d_in[0];
    const float* dec      = (const float*)d_in[1];
    const float* W_enc    = (const float*)d_in[2];
    const float* b_enc    = (const float*)d_in[3];
    const float* W_dec    = (const float*)d_in[4];
    const float* b_dec    = (const float*)d_in[5];
    const float* W_fc     = (const float*)d_in[6];
    const float* b_fc     = (const float*)d_in[7];
    const int*   enc_lens = (const int*)d_in[8];
    const int*   dec_lens = (const int*)d_in[9];
    float* out = (float*)d_out;
    (void)in_sizes; (void)n_in; (void)out_size;

    cudaFuncSetAttribute(proj_mma,
                         cudaFuncAttributeMaxDynamicSharedMemorySize, SMEM_GEMM);
    cudaFuncSetAttribute(joint_gemm_mma,
                         cudaFuncAttributeMaxDynamicSharedMemorySize, SMEM_GEMM);

    // Stage inputs: 3 weight transposes (bf16) + enc/dec bf16 convert
    prep<<<2368, 256>>>(W_fc, W_enc, W_dec, enc, dec);
    // g_proj = concat(enc,dec)_bf16 @ {W_enc,W_dec}^T + bias  (tensor cores)
    proj_mma<<<dim3(F_/128, MPROJ/128), 256, SMEM_GEMM>>>(b_enc, b_dec);
    // A = bf16(tanh(pe (+) pd))  — dead rows skipped
    build_A<<<B_*T_, 256>>>(enc_lens, dec_lens);
    // logits(fp16) = A @ WT^T  — live rows PACKED in M
    joint_gemm_mma<<<dim3(V_/128, ROWS_/128), 256, SMEM_GEMM>>>(enc_lens, dec_lens);
    // out = log_softmax(logits + b_fc) with length masking
    softmax_mask_kernel<<<ROWS_/8, 256>>>(b_fc, enc_lens, dec_lens, out);
}